// round 3
// baseline (speedup 1.0000x reference)
#include <cuda_runtime.h>
#include <cuda_fp16.h>
#include <cstdint>
#include <cstddef>

#define S_LEN 128
#define BATCH 32
#define HID   200
#define EMB   200
#define VOCAB 50257
#define KP    208              // K padded to multiple of 16 for mma
#define M_TOT (S_LEN*BATCH)    // 4096
#define RNN_CTAS 50

// ---------------- scratch (device globals; no allocation) ----------------
__device__ float  g_Z0[M_TOT*HID];
__device__ float  g_Z1[M_TOT*HID];
__device__ float  g_Y0[M_TOT*HID];
__device__ float  g_Y1[M_TOT*HID];
__device__ __half g_A16[M_TOT*KP];
__device__ __half g_B16[(size_t)VOCAB*KP];
__device__ unsigned g_bar[256];   // zero-initialized; self-resetting protocol

// ---------------- barrier primitives ----------------
__device__ __forceinline__ void bar_arrive(unsigned* p) {
    asm volatile("red.release.gpu.global.add.u32 [%0], 1;" :: "l"(p) : "memory");
}
__device__ __forceinline__ unsigned bar_ld(unsigned* p) {
    unsigned v;
    asm volatile("ld.acquire.gpu.global.u32 %0, [%1];" : "=r"(v) : "l"(p) : "memory");
    return v;
}

// ---------------- K1: embedding gather + Z0 = emb @ W_ih0^T ----------------
__global__ void z0_kernel(const int* __restrict__ X, const float* __restrict__ embW,
                          const float* __restrict__ Wih) {
    __shared__ float xs[BATCH][KP];
    int s = blockIdx.x, tid = threadIdx.x;
    for (int i = tid; i < BATCH*EMB; i += 256) {
        int b = i / EMB, d = i % EMB;
        xs[b][d] = embW[(size_t)X[s*BATCH + b]*EMB + d];
    }
    __syncthreads();
    int b = tid & 31, jg = tid >> 5;       // 8 j-groups x 25 j's = 200
    for (int jj = 0; jj < 25; jj++) {
        int j = jg*25 + jj;
        const float4* wr = (const float4*)(Wih + (size_t)j*EMB);
        const float4* xr = (const float4*)&xs[b][0];
        float acc = 0.f;
        #pragma unroll 10
        for (int k4 = 0; k4 < EMB/4; k4++) {
            float4 w = wr[k4], x = xr[k4];
            acc += w.x*x.x + w.y*x.y + w.z*x.z + w.w*x.w;
        }
        g_Z0[(s*BATCH + b)*HID + j] = acc;
    }
}

// ---------------- K3: Z1 = y0 @ W_ih1^T ----------------
__global__ void z1_kernel(const float* __restrict__ Wih) {
    __shared__ float xs[BATCH][KP];
    int s = blockIdx.x, tid = threadIdx.x;
    for (int i = tid; i < BATCH*HID; i += 256) {
        int b = i / HID, d = i % HID;
        xs[b][d] = g_Y0[(s*BATCH + b)*HID + d];
    }
    __syncthreads();
    int b = tid & 31, jg = tid >> 5;
    for (int jj = 0; jj < 25; jj++) {
        int j = jg*25 + jj;
        const float4* wr = (const float4*)(Wih + (size_t)j*HID);
        const float4* xr = (const float4*)&xs[b][0];
        float acc = 0.f;
        #pragma unroll 10
        for (int k4 = 0; k4 < HID/4; k4++) {
            float4 w = wr[k4], x = xr[k4];
            acc += w.x*x.x + w.y*x.y + w.z*x.z + w.w*x.w;
        }
        g_Z1[(s*BATCH + b)*HID + j] = acc;
    }
}

// ---------------- K2/K4: persistent recurrence with software grid barrier ----------------
// grid = 50 CTAs x 128 threads. CTA owns 4 output neurons (j), thread = (b, j).
__global__ void rnn_kernel(const float* __restrict__ Whh, const float* __restrict__ h_init,
                           int layer) {
    const float* Z = layer ? g_Z1 : g_Z0;
    float*       Y = layer ? g_Y1 : g_Y0;
    const int bar_base = layer ? S_LEN : 0;

    int tid = threadIdx.x;
    int b = tid & 31, jr = tid >> 5;
    int j = blockIdx.x*4 + jr;

    __shared__ float Wsh[4][HID];
    for (int i = tid; i < 4*HID; i += 128)
        Wsh[i/HID][i%HID] = Whh[(size_t)(blockIdx.x*4 + i/HID)*HID + (i%HID)];
    __syncthreads();

    const float4* wr = (const float4*)&Wsh[jr][0];

    for (int t = 0; t < S_LEN; t++) {
        const float* hp = (t == 0) ? h_init : (Y + (t-1)*BATCH*HID);
        const float4* hr = (const float4*)(hp + b*HID);
        float acc = Z[(t*BATCH + b)*HID + j];
        #pragma unroll 10
        for (int k4 = 0; k4 < HID/4; k4++) {
            float4 h = hr[k4], w = wr[k4];
            acc += h.x*w.x + h.y*w.y + h.z*w.z + h.w*w.w;
        }
        Y[(t*BATCH + b)*HID + j] = tanhf(acc);
        __syncthreads();
        if (tid == 0) {
            __threadfence();
            unsigned* bp = &g_bar[bar_base + t];
            bar_arrive(bp);
            while (bar_ld(bp) < (unsigned)RNN_CTAS) { }
            if (blockIdx.x == 0) {
                int idx = bar_base + t;
                // reset the previous barrier slot (everyone has passed it);
                // slot 255 is reset at the start of the next launch/replay.
                if (idx > 0) g_bar[idx-1] = 0;
                else         g_bar[255]   = 0;
            }
        }
        __syncthreads();
    }
}

// ---------------- fp16 conversions ----------------
__global__ void convA_kernel() {
    int idx = blockIdx.x*256 + threadIdx.x;
    if (idx >= M_TOT*KP) return;
    int r = idx / KP, c = idx % KP;
    g_A16[idx] = (c < HID) ? __float2half_rn(g_Y1[r*HID + c]) : __float2half_rn(0.f);
}
__global__ void convB_kernel(const float* __restrict__ W) {
    size_t idx = (size_t)blockIdx.x*256 + threadIdx.x;
    if (idx >= (size_t)VOCAB*KP) return;
    size_t r = idx / KP; int c = (int)(idx % KP);
    g_B16[idx] = (c < HID) ? __float2half_rn(W[r*HID + c]) : __float2half_rn(0.f);
}

// ---------------- hidden_out = stack(y0[S-1], y1[S-1]) ----------------
__global__ void hidden_kernel(float* __restrict__ out) {
    int idx = blockIdx.x*256 + threadIdx.x;
    if (idx >= 2*BATCH*HID) return;
    int l = idx / (BATCH*HID), r = idx % (BATCH*HID);
    const float* Y = l ? g_Y1 : g_Y0;
    out[(size_t)M_TOT*VOCAB + idx] = Y[(S_LEN-1)*BATCH*HID + r];
}

// ---------------- K5: decode GEMM, fp16 mma.sync, fp32 accumulate ----------------
// C[4096, 50257] = A16[4096, 208] * B16[50257, 208]^T + bias
// CTA tile 128x128, full K resident in smem (no k-loop over tiles).
#define SST 216   // smem row stride in halves (conflict-mitigating pad)
__global__ __launch_bounds__(256, 2) void decode_kernel(const float* __restrict__ bias,
                                                        float* __restrict__ out) {
    extern __shared__ __half smemh[];
    __half* As = smemh;             // [128][SST]
    __half* Bs = smemh + 128*SST;   // [128][SST]
    int tid = threadIdx.x;
    int bn = blockIdx.x, bm = blockIdx.y;

    // A tile: 128 rows x 208 halves = 128 x 26 uint4
    for (int i = tid; i < 128*26; i += 256) {
        int r = i/26, c = i%26;
        uint4 v = *(const uint4*)(g_A16 + (size_t)(bm*128 + r)*KP + c*8);
        *(uint4*)(As + r*SST + c*8) = v;
    }
    // B tile (guard tail of V)
    for (int i = tid; i < 128*26; i += 256) {
        int r = i/26, c = i%26;
        int gn = bn*128 + r;
        uint4 v = make_uint4(0u,0u,0u,0u);
        if (gn < VOCAB) v = *(const uint4*)(g_B16 + (size_t)gn*KP + c*8);
        *(uint4*)(Bs + r*SST + c*8) = v;
    }
    __syncthreads();

    int warp = tid >> 5, lane = tid & 31;
    int wm = warp >> 2, wn = warp & 3;     // 2 x 4 warp grid, warp tile 64x32
    int lr = lane >> 2, lc = lane & 3;

    float acc[4][4][4];
    #pragma unroll
    for (int a=0;a<4;a++)
        #pragma unroll
        for (int b=0;b<4;b++)
            #pragma unroll
            for (int c=0;c<4;c++) acc[a][b][c]=0.f;

    const __half* Abase = As + (size_t)(wm*64 + lr)*SST + lc*2;
    const __half* Bbase = Bs + (size_t)(wn*32 + lr)*SST + lc*2;

    for (int ks = 0; ks < 13; ks++) {
        int k0 = ks*16;
        uint32_t a[4][4], bf[4][2];
        #pragma unroll
        for (int mf = 0; mf < 4; mf++) {
            const __half* p = Abase + (size_t)mf*16*SST + k0;
            a[mf][0] = *(const uint32_t*)(p);
            a[mf][1] = *(const uint32_t*)(p + 8*SST);
            a[mf][2] = *(const uint32_t*)(p + 8);
            a[mf][3] = *(const uint32_t*)(p + 8*SST + 8);
        }
        #pragma unroll
        for (int nf = 0; nf < 4; nf++) {
            const __half* p = Bbase + (size_t)nf*8*SST + k0;
            bf[nf][0] = *(const uint32_t*)(p);
            bf[nf][1] = *(const uint32_t*)(p + 8);
        }
        #pragma unroll
        for (int mf = 0; mf < 4; mf++)
            #pragma unroll
            for (int nf = 0; nf < 4; nf++)
                asm volatile(
                    "mma.sync.aligned.m16n8k16.row.col.f32.f16.f16.f32 "
                    "{%0,%1,%2,%3}, {%4,%5,%6,%7}, {%8,%9}, {%0,%1,%2,%3};"
                    : "+f"(acc[mf][nf][0]), "+f"(acc[mf][nf][1]),
                      "+f"(acc[mf][nf][2]), "+f"(acc[mf][nf][3])
                    : "r"(a[mf][0]), "r"(a[mf][1]), "r"(a[mf][2]), "r"(a[mf][3]),
                      "r"(bf[nf][0]), "r"(bf[nf][1]));
    }

    #pragma unroll
    for (int mf = 0; mf < 4; mf++) {
        int gm = bm*128 + wm*64 + mf*16 + lr;
        #pragma unroll
        for (int nf = 0; nf < 4; nf++) {
            int gn = bn*128 + wn*32 + nf*8 + lc*2;
            if (gn < VOCAB) {
                float b0 = bias[gn];
                out[(size_t)gm*VOCAB + gn]     = acc[mf][nf][0] + b0;
                out[(size_t)(gm+8)*VOCAB + gn] = acc[mf][nf][2] + b0;
            }
            if (gn+1 < VOCAB) {
                float b1 = bias[gn+1];
                out[(size_t)gm*VOCAB + gn+1]     = acc[mf][nf][1] + b1;
                out[(size_t)(gm+8)*VOCAB + gn+1] = acc[mf][nf][3] + b1;
            }
        }
    }
}

// ---------------- launch ----------------
extern "C" void kernel_launch(void* const* d_in, const int* in_sizes, int n_in,
                              void* d_out, int out_size) {
    (void)in_sizes; (void)n_in; (void)out_size;
    const int*   X      = (const int*)d_in[0];
    const float* hidden = (const float*)d_in[1];
    const float* embW   = (const float*)d_in[2];
    const float* Wih0   = (const float*)d_in[3];
    const float* Whh0   = (const float*)d_in[4];
    const float* Wih1   = (const float*)d_in[5];
    const float* Whh1   = (const float*)d_in[6];
    const float* decW   = (const float*)d_in[7];
    const float* decb   = (const float*)d_in[8];
    float* out = (float*)d_out;

    z0_kernel<<<S_LEN, 256>>>(X, embW, Wih0);
    rnn_kernel<<<RNN_CTAS, 128>>>(Whh0, hidden, 0);
    z1_kernel<<<S_LEN, 256>>>(Wih1);
    rnn_kernel<<<RNN_CTAS, 128>>>(Whh1, hidden + BATCH*HID, 1);

    convA_kernel<<<(M_TOT*KP + 255)/256, 256>>>();
    convB_kernel<<<(int)(((size_t)VOCAB*KP + 255)/256), 256>>>(decW);
    hidden_kernel<<<(2*BATCH*HID + 255)/256, 256>>>(out);

    cudaFuncSetAttribute(decode_kernel, cudaFuncAttributeMaxDynamicSharedMemorySize,
                         2*128*SST*(int)sizeof(__half));
    dim3 grid((VOCAB + 127)/128, M_TOT/128);   // 393 x 32
    decode_kernel<<<grid, 256, 2*128*SST*(int)sizeof(__half)>>>(decb, out);
}

// round 9
// speedup vs baseline: 2.8646x; 2.8646x over previous
#include <cuda_runtime.h>
#include <cuda_fp16.h>
#include <cstdint>
#include <cstddef>

#define S_LEN 128
#define BATCH 32
#define HID   200
#define EMB   200
#define VOCAB 50257
#define KP    208              // K padded to multiple of 16 for mma
#define M_TOT (S_LEN*BATCH)    // 4096

// ---------------- scratch (device globals; no allocation) ----------------
__device__ float  g_Z0[M_TOT*HID];
__device__ float  g_Z1[M_TOT*HID];
__device__ float  g_Y0[M_TOT*HID];
__device__ float  g_Y1[M_TOT*HID];
__device__ __half g_A16[M_TOT*KP];          // pad cols [200,208) stay zero (static init, never written)
__device__ __half g_B16[(size_t)VOCAB*KP];

// ---------------- K1: embedding gather + Z0 = emb @ W_ih0^T ----------------
__global__ void z0_kernel(const int* __restrict__ X, const float* __restrict__ embW,
                          const float* __restrict__ Wih) {
    __shared__ __align__(16) float xs[BATCH][KP];
    int s = blockIdx.x, tid = threadIdx.x;
    for (int i = tid; i < BATCH*EMB; i += 256) {
        int b = i / EMB, d = i % EMB;
        xs[b][d] = embW[(size_t)X[s*BATCH + b]*EMB + d];
    }
    __syncthreads();
    int b = tid & 31, jg = tid >> 5;       // 8 j-groups x 25 j's = 200
    for (int jj = 0; jj < 25; jj++) {
        int j = jg*25 + jj;
        const float4* wr = (const float4*)(Wih + (size_t)j*EMB);
        const float4* xr = (const float4*)&xs[b][0];
        float acc = 0.f;
        #pragma unroll 10
        for (int k4 = 0; k4 < EMB/4; k4++) {
            float4 w = wr[k4], x = xr[k4];
            acc += w.x*x.x + w.y*x.y + w.z*x.z + w.w*x.w;
        }
        g_Z0[(s*BATCH + b)*HID + j] = acc;
    }
}

// ---------------- K3: Z1 = y0 @ W_ih1^T (parallel over all timesteps) ----------------
__global__ void z1_kernel(const float* __restrict__ Wih) {
    __shared__ __align__(16) float xs[BATCH][KP];
    int s = blockIdx.x, tid = threadIdx.x;
    for (int i = tid; i < BATCH*HID; i += 256) {
        int b = i / HID, d = i % HID;
        xs[b][d] = g_Y0[(s*BATCH + b)*HID + d];
    }
    __syncthreads();
    int b = tid & 31, jg = tid >> 5;
    for (int jj = 0; jj < 25; jj++) {
        int j = jg*25 + jj;
        const float4* wr = (const float4*)(Wih + (size_t)j*HID);
        const float4* xr = (const float4*)&xs[b][0];
        float acc = 0.f;
        #pragma unroll 10
        for (int k4 = 0; k4 < HID/4; k4++) {
            float4 w = wr[k4], x = xr[k4];
            acc += w.x*x.x + w.y*x.y + w.z*x.z + w.w*x.w;
        }
        g_Z1[(s*BATCH + b)*HID + j] = acc;
    }
}

// ---------------- K2/K4: batch-parallel recurrence. One CTA per batch row. ----------------
// Thread t0: j = t0>>1 (output neuron), kh = t0&1 (k half). W_hh row-half pinned in
// 100 registers per thread for all 128 steps; h double-buffered in smem;
// ONE __syncthreads per step. Scratch globals selected DEVICE-SIDE via `layer`
// (never pass __device__ symbols as kernel args from host!).
#define RNN_THREADS 416
__global__ __launch_bounds__(RNN_THREADS, 1)
void rnn_fast_kernel(const float* __restrict__ Whh, const float* __restrict__ h_init,
                     int layer) {
    __shared__ __align__(16) float hs[2][HID];
    const float* __restrict__ Z = layer ? g_Z1 : g_Z0;
    float* __restrict__ Y       = layer ? g_Y1 : g_Y0;

    const int b   = blockIdx.x;
    const int t0  = threadIdx.x;
    const int j   = t0 >> 1;
    const int kh  = t0 & 1;
    const bool valid = (j < HID);

    // Pin this thread's W_hh row-half in registers (clamped in-bounds for j>=HID).
    const float* wp = Whh + (size_t)(valid ? j : 0)*HID + kh*100;
    float w[100];
    #pragma unroll
    for (int i = 0; i < 100; i++) w[i] = wp[i];

    // init h buffer 0 from h_init
    for (int i = t0; i < HID; i += RNN_THREADS) hs[0][i] = h_init[b*HID + i];
    __syncthreads();

    // Z prefetch one step ahead (off the dependent chain)
    float zc = (valid && kh == 0) ? Z[(size_t)b*HID + j] : 0.f;

    for (int t = 0; t < S_LEN; t++) {
        const int cur = t & 1, nxt = cur ^ 1;
        float zn = 0.f;
        if (t + 1 < S_LEN && valid && kh == 0)
            zn = Z[((size_t)(t+1)*BATCH + b)*HID + j];

        // 100-MAC half-dot: 4 independent accumulator chains, broadcast LDS.128
        float a0 = 0.f, a1 = 0.f, a2 = 0.f, a3 = 0.f;
        const float4* h4 = (const float4*)(hs[cur] + kh*100);
        #pragma unroll
        for (int i = 0; i < 25; i++) {
            float4 h = h4[i];
            a0 += w[4*i+0]*h.x;
            a1 += w[4*i+1]*h.y;
            a2 += w[4*i+2]*h.z;
            a3 += w[4*i+3]*h.w;
        }
        float acc = (a0 + a1) + (a2 + a3);
        // pair (2j, 2j+1) is within one warp; kh=1 partial -> kh=0 lane
        float other = __shfl_down_sync(0xffffffffu, acc, 1);
        if (valid && kh == 0) {
            float v = tanhf(zc + acc + other);
            hs[nxt][j] = v;                                   // write OTHER buffer
            Y[((size_t)t*BATCH + b)*HID + j] = v;
            if (layer)
                g_A16[((size_t)t*BATCH + b)*KP + j] = __float2half_rn(v);
        }
        zc = zn;
        __syncthreads();   // h_new visible; next step reads hs[nxt]
    }
}

// ---------------- convB: decoder weights -> fp16, K padded to 208 ----------------
__global__ void convB_kernel(const float* __restrict__ W) {
    size_t idx = (size_t)blockIdx.x*256 + threadIdx.x;
    if (idx >= (size_t)VOCAB*KP) return;
    size_t r = idx / KP; int c = (int)(idx % KP);
    g_B16[idx] = (c < HID) ? __float2half_rn(W[r*HID + c]) : __float2half_rn(0.f);
}

// ---------------- hidden_out = stack(y0[S-1], y1[S-1]) ----------------
__global__ void hidden_kernel(float* __restrict__ out) {
    int idx = blockIdx.x*256 + threadIdx.x;
    if (idx >= 2*BATCH*HID) return;
    int l = idx / (BATCH*HID), r = idx % (BATCH*HID);
    const float* Y = l ? g_Y1 : g_Y0;
    out[(size_t)M_TOT*VOCAB + idx] = Y[(S_LEN-1)*BATCH*HID + r];
}

// ---------------- K5: decode GEMM, fp16 mma.sync, fp32 accumulate ----------------
// C[4096, 50257] = A16[4096, 208] * B16[50257, 208]^T + bias
#define SST 216   // smem row stride in halves (conflict-mitigating pad)
__global__ __launch_bounds__(256, 2) void decode_kernel(const float* __restrict__ bias,
                                                        float* __restrict__ out) {
    extern __shared__ __half smemh[];
    __half* As = smemh;             // [128][SST]
    __half* Bs = smemh + 128*SST;   // [128][SST]
    int tid = threadIdx.x;
    int bn = blockIdx.x, bm = blockIdx.y;

    for (int i = tid; i < 128*26; i += 256) {
        int r = i/26, c = i%26;
        uint4 v = *(const uint4*)(g_A16 + (size_t)(bm*128 + r)*KP + c*8);
        *(uint4*)(As + r*SST + c*8) = v;
    }
    for (int i = tid; i < 128*26; i += 256) {
        int r = i/26, c = i%26;
        int gn = bn*128 + r;
        uint4 v = make_uint4(0u,0u,0u,0u);
        if (gn < VOCAB) v = *(const uint4*)(g_B16 + (size_t)gn*KP + c*8);
        *(uint4*)(Bs + r*SST + c*8) = v;
    }
    __syncthreads();

    int warp = tid >> 5, lane = tid & 31;
    int wm = warp >> 2, wn = warp & 3;     // 2 x 4 warp grid, warp tile 64x32
    int lr = lane >> 2, lc = lane & 3;

    float acc[4][4][4];
    #pragma unroll
    for (int a=0;a<4;a++)
        #pragma unroll
        for (int b=0;b<4;b++)
            #pragma unroll
            for (int c=0;c<4;c++) acc[a][b][c]=0.f;

    const __half* Abase = As + (size_t)(wm*64 + lr)*SST + lc*2;
    const __half* Bbase = Bs + (size_t)(wn*32 + lr)*SST + lc*2;

    for (int ks = 0; ks < 13; ks++) {
        int k0 = ks*16;
        uint32_t a[4][4], bf[4][2];
        #pragma unroll
        for (int mf = 0; mf < 4; mf++) {
            const __half* p = Abase + (size_t)mf*16*SST + k0;
            a[mf][0] = *(const uint32_t*)(p);
            a[mf][1] = *(const uint32_t*)(p + 8*SST);
            a[mf][2] = *(const uint32_t*)(p + 8);
            a[mf][3] = *(const uint32_t*)(p + 8*SST + 8);
        }
        #pragma unroll
        for (int nf = 0; nf < 4; nf++) {
            const __half* p = Bbase + (size_t)nf*8*SST + k0;
            bf[nf][0] = *(const uint32_t*)(p);
            bf[nf][1] = *(const uint32_t*)(p + 8);
        }
        #pragma unroll
        for (int mf = 0; mf < 4; mf++)
            #pragma unroll
            for (int nf = 0; nf < 4; nf++)
                asm volatile(
                    "mma.sync.aligned.m16n8k16.row.col.f32.f16.f16.f32 "
                    "{%0,%1,%2,%3}, {%4,%5,%6,%7}, {%8,%9}, {%0,%1,%2,%3};"
                    : "+f"(acc[mf][nf][0]), "+f"(acc[mf][nf][1]),
                      "+f"(acc[mf][nf][2]), "+f"(acc[mf][nf][3])
                    : "r"(a[mf][0]), "r"(a[mf][1]), "r"(a[mf][2]), "r"(a[mf][3]),
                      "r"(bf[nf][0]), "r"(bf[nf][1]));
    }

    #pragma unroll
    for (int mf = 0; mf < 4; mf++) {
        int gm = bm*128 + wm*64 + mf*16 + lr;
        #pragma unroll
        for (int nf = 0; nf < 4; nf++) {
            int gn = bn*128 + wn*32 + nf*8 + lc*2;
            if (gn < VOCAB) {
                float b0 = bias[gn];
                out[(size_t)gm*VOCAB + gn]     = acc[mf][nf][0] + b0;
                out[(size_t)(gm+8)*VOCAB + gn] = acc[mf][nf][2] + b0;
            }
            if (gn+1 < VOCAB) {
                float b1 = bias[gn+1];
                out[(size_t)gm*VOCAB + gn+1]     = acc[mf][nf][1] + b1;
                out[(size_t)(gm+8)*VOCAB + gn+1] = acc[mf][nf][3] + b1;
            }
        }
    }
}

// ---------------- launch ----------------
extern "C" void kernel_launch(void* const* d_in, const int* in_sizes, int n_in,
                              void* d_out, int out_size) {
    (void)in_sizes; (void)n_in; (void)out_size;
    const int*   X      = (const int*)d_in[0];
    const float* hidden = (const float*)d_in[1];
    const float* embW   = (const float*)d_in[2];
    const float* Wih0   = (const float*)d_in[3];
    const float* Whh0   = (const float*)d_in[4];
    const float* Wih1   = (const float*)d_in[5];
    const float* Whh1   = (const float*)d_in[6];
    const float* decW   = (const float*)d_in[7];
    const float* decb   = (const float*)d_in[8];
    float* out = (float*)d_out;

    // Independent prep first
    convB_kernel<<<(int)(((size_t)VOCAB*KP + 255)/256), 256>>>(decW);
    z0_kernel<<<S_LEN, 256>>>(X, embW, Wih0);

    // Layer 0 recurrence (batch-parallel, smem h, register W)
    rnn_fast_kernel<<<BATCH, RNN_THREADS>>>(Whh0, hidden, 0);

    // Layer-1 input projection (parallel over timesteps)
    z1_kernel<<<S_LEN, 256>>>(Wih1);

    // Layer 1 recurrence; writes fp16 A16 directly (pad cols stay zero)
    rnn_fast_kernel<<<BATCH, RNN_THREADS>>>(Whh1, hidden + BATCH*HID, 1);

    hidden_kernel<<<(2*BATCH*HID + 255)/256, 256>>>(out);

    cudaFuncSetAttribute(decode_kernel, cudaFuncAttributeMaxDynamicSharedMemorySize,
                         2*128*SST*(int)sizeof(__half));
    dim3 grid((VOCAB + 127)/128, M_TOT/128);   // 393 x 32
    decode_kernel<<<grid, 256, 2*128*SST*(int)sizeof(__half)>>>(decb, out);
}